// round 4
// baseline (speedup 1.0000x reference)
#include <cuda_runtime.h>
#include <math.h>
#include <stdint.h>

// ---------------- problem constants ----------------
namespace {
constexpr int NN   = 30000;   // nodes
constexpr int NE   = 480000;  // edges
constexpr int C    = 128;     // channels (= F)
constexpr int KG   = 8;       // gaussians
constexpr int LL   = 4;       // layers
constexpr int H    = 256;     // LSTM hidden
constexpr int H4   = 1024;    // 4*H
constexpr int NHID = 512;
constexpr int NOUT = 256;
constexpr int NB   = 1024;    // graphs
}

// ---------------- scratch (device globals; no allocations allowed) -------
__device__ __align__(256) float d_h[NN * C];
__device__ __align__(256) float d_hl[LL][NN * C];
__device__ __align__(256) float d_xg[NN * KG * C];
__device__ __align__(256) float d_ew[NE * KG];
__device__ __align__(256) float d_hr[NN * C];
__device__ __align__(256) float d_bns[C];
__device__ __align__(256) float d_bnq[C];
__device__ __align__(256) float d_lh[2][2][NN * H];   // [pingpong][dir]
__device__ __align__(256) float d_lc[2][NN * H];      // [dir]
__device__ __align__(256) float d_af[5 * NN];
__device__ __align__(256) float d_ab[5 * NN];
__device__ __align__(256) float d_nrep[NN * C];
__device__ __align__(256) float d_cnt[NB];
__device__ __align__(256) float d_hg[NB * C];
__device__ __align__(256) float d_z1[NB * NHID];
__device__ __align__(256) float d_z2[NB * NOUT];
// CSR scratch
__device__ __align__(256) int d_indeg[NN];
__device__ __align__(256) int d_rowptr[NN + 1];
__device__ __align__(256) int d_curp[NN];
__device__ __align__(256) int d_eid[NE];
__device__ __align__(256) int d_esrc[NE];

// ---------------- TF32 helpers ----------------
__device__ __forceinline__ uint32_t f2tf(float f) {
    uint32_t u;
    asm("cvt.rna.tf32.f32 %0, %1;" : "=r"(u) : "f"(f));
    return u;
}
__device__ __forceinline__ uint32_t tfw(uint32_t rawbits) {
    return f2tf(__uint_as_float(rawbits));
}
__device__ __forceinline__ void mma8(float* c, const uint32_t* a, const uint32_t* b) {
    asm volatile(
        "mma.sync.aligned.m16n8k8.row.col.f32.tf32.tf32.f32 "
        "{%0,%1,%2,%3}, {%4,%5,%6,%7}, {%8,%9}, {%0,%1,%2,%3};"
        : "+f"(c[0]), "+f"(c[1]), "+f"(c[2]), "+f"(c[3])
        : "r"(a[0]), "r"(a[1]), "r"(a[2]), "r"(a[3]), "r"(b[0]), "r"(b[1]));
}
__device__ __forceinline__ void cpa16(uint32_t sdst, const void* gsrc, int srcsz) {
    asm volatile("cp.async.ca.shared.global [%0], [%1], 16, %2;\n"
                 :: "r"(sdst), "l"(gsrc), "r"(srcsz));
}
__device__ __forceinline__ void cpa_commit() { asm volatile("cp.async.commit_group;\n"); }
__device__ __forceinline__ void cpa_wait1()  { asm volatile("cp.async.wait_group 1;\n"); }
__device__ __forceinline__ float sigf(float x) { return 1.f / (1.f + expf(-x)); }

// ---------------- generic TF32 GEMM (cp.async 2-stage), as in R3 ----------
struct GA {
    const float* A;   // [M, Kd]
    const float* B;   // TB: [Nm, Kd]  else [Kd, Nm]
    const float* A2;  // [M, Kd2] (TB only)
    const float* B2;  // [Nm, Kd2]
    float* Cm;        // [M, Nm]
};

template <bool TB, bool ACC, bool RELU_, bool BIAS_>
__global__ __launch_bounds__(256) void tgemm(
    GA g0, GA g1, const float* __restrict__ bias, int M, int Nm, int Kd, int Kd2)
{
    __shared__ uint32_t As[2][128 * 20];
    __shared__ uint32_t Bs[2][2560];

    const GA ga = blockIdx.z ? g1 : g0;
    const float* __restrict__ A  = ga.A;
    const float* __restrict__ B  = ga.B;
    const float* __restrict__ A2 = ga.A2;
    const float* __restrict__ B2 = ga.B2;
    float* __restrict__ Cm = ga.Cm;

    const int tid  = threadIdx.x;
    const int lane = tid & 31;
    const int wid  = tid >> 5;
    const int wm   = wid & 3;
    const int wn   = wid >> 2;
    const int gid  = lane >> 2;
    const int tig  = lane & 3;
    const int row0 = blockIdx.y * 128, col0 = blockIdx.x * 128;

    const int nt1 = Kd >> 4;
    const int nt  = nt1 + (Kd2 >> 4);

    float acc[2][8][4];
#pragma unroll
    for (int mi = 0; mi < 2; mi++)
#pragma unroll
        for (int ni = 0; ni < 8; ni++)
#pragma unroll
            for (int r = 0; r < 4; r++) acc[mi][ni][r] = 0.f;

    const int lr0 = tid >> 2, lc4 = (tid & 3) * 4;

    auto loadTile = [&](int t, int st) {
        const float* Ap; const float* Bp; int Kc, k0;
        if (t < nt1) { Ap = A;  Bp = B;  Kc = Kd;  k0 = t << 4; }
        else         { Ap = A2; Bp = B2; Kc = Kd2; k0 = (t - nt1) << 4; }
#pragma unroll
        for (int it = 0; it < 2; it++) {
            int rr = lr0 + it * 64;
            int gr = row0 + rr;
            uint32_t dst = (uint32_t)__cvta_generic_to_shared(&As[st][rr * 20 + lc4]);
            cpa16(dst, Ap + (size_t)gr * Kc + k0 + lc4, gr < M ? 16 : 0);
        }
        if (TB) {
#pragma unroll
            for (int it = 0; it < 2; it++) {
                int rr = lr0 + it * 64;
                uint32_t dst = (uint32_t)__cvta_generic_to_shared(&Bs[st][rr * 20 + lc4]);
                cpa16(dst, Bp + (size_t)(col0 + rr) * Kc + k0 + lc4, 16);
            }
        } else {
#pragma unroll
            for (int it = 0; it < 2; it++) {
                int idx = tid + it * 256;
                int kk = idx >> 5, n4 = (idx & 31) * 4;
                uint32_t dst = (uint32_t)__cvta_generic_to_shared(&Bs[st][kk * 136 + n4]);
                cpa16(dst, Bp + (size_t)(k0 + kk) * Nm + col0 + n4, 16);
            }
        }
    };

    loadTile(0, 0);
    cpa_commit();

    for (int t = 0; t < nt; t++) {
        if (t + 1 < nt) loadTile(t + 1, (t + 1) & 1);
        cpa_commit();
        cpa_wait1();
        __syncthreads();

        const int st = t & 1;
#pragma unroll
        for (int kk = 0; kk < 16; kk += 8) {
            uint32_t a[2][4], b[8][2];
#pragma unroll
            for (int mi = 0; mi < 2; mi++) {
                int mr = wm * 32 + mi * 16;
                a[mi][0] = tfw(As[st][(mr + gid)     * 20 + kk + tig]);
                a[mi][1] = tfw(As[st][(mr + gid + 8) * 20 + kk + tig]);
                a[mi][2] = tfw(As[st][(mr + gid)     * 20 + kk + tig + 4]);
                a[mi][3] = tfw(As[st][(mr + gid + 8) * 20 + kk + tig + 4]);
            }
#pragma unroll
            for (int ni = 0; ni < 8; ni++) {
                int nr = wn * 64 + ni * 8;
                if (TB) {
                    b[ni][0] = tfw(Bs[st][(nr + gid) * 20 + kk + tig]);
                    b[ni][1] = tfw(Bs[st][(nr + gid) * 20 + kk + tig + 4]);
                } else {
                    b[ni][0] = tfw(Bs[st][(kk + tig)     * 136 + nr + gid]);
                    b[ni][1] = tfw(Bs[st][(kk + tig + 4) * 136 + nr + gid]);
                }
            }
#pragma unroll
            for (int mi = 0; mi < 2; mi++)
#pragma unroll
                for (int ni = 0; ni < 8; ni++)
                    mma8(acc[mi][ni], a[mi], b[ni]);
        }
        __syncthreads();
    }

#pragma unroll
    for (int mi = 0; mi < 2; mi++) {
#pragma unroll
        for (int half = 0; half < 2; half++) {
            int r = row0 + wm * 32 + mi * 16 + gid + half * 8;
            if (r >= M) continue;
#pragma unroll
            for (int ni = 0; ni < 8; ni++) {
                int cI = col0 + wn * 64 + ni * 8 + tig * 2;
                float v0 = acc[mi][ni][half * 2 + 0];
                float v1 = acc[mi][ni][half * 2 + 1];
                float* cp = Cm + (size_t)r * Nm + cI;
                if (ACC)   { v0 += cp[0]; v1 += cp[1]; }
                if (BIAS_) { v0 += bias[cI]; v1 += bias[cI + 1]; }
                if (RELU_) { v0 = fmaxf(v0, 0.f); v1 = fmaxf(v1, 0.f); }
                cp[0] = v0; cp[1] = v1;
            }
        }
    }
}

// ---------------- fused LSTM step: GEMM + cell + attention dot ----------
// Tile: 128 node rows x (4 gates x 32 hidden). grid = (H/32, ceil(NN/128), 2).
// gates = xs@Wih^T + lh_prev@Whh^T ; cell update in epilogue; lh double-buffered.
__global__ __launch_bounds__(256) void tlstm(
    const float* __restrict__ xf, const float* __restrict__ xb,
    const float* __restrict__ wih, const float* __restrict__ whh,
    const float* __restrict__ bih, const float* __restrict__ bhh,
    const float* __restrict__ attw, int K2, int s)
{
    __shared__ __align__(16) uint32_t sraw[10240];   // 40KB: As(2x2560) + Bs(2x2560)
    uint32_t* Asb = sraw;            // As[st] = Asb + st*2560, [m][k] stride 20
    uint32_t* Bsb = sraw + 5120;     // Bs[st] = Bsb + st*2560, [tilecol][k] stride 20
    float* gbuf = (float*)sraw;      // epilogue reuse: [64][133] = 34KB

    const int dir  = blockIdx.z;
    const int c0   = blockIdx.x * 32;     // hidden slice base
    const int row0 = blockIdx.y * 128;
    const int pb   = s & 1;                // lh read buffer; write to 1-pb

    const float* A  = dir ? xb : xf;
    const float* B  = wih + (size_t)dir * H4 * C;
    const float* A2 = d_lh[pb][dir];
    const float* B2 = whh + (size_t)dir * H4 * H;

    const int tid  = threadIdx.x;
    const int lane = tid & 31;
    const int wid  = tid >> 5;
    const int wm   = wid & 3;
    const int wn   = wid >> 2;
    const int gid  = lane >> 2;
    const int tig  = lane & 3;

    const int nt1 = C >> 4;            // 8
    const int nt  = nt1 + (K2 >> 4);   // 8 or 24

    float acc[2][8][4];
#pragma unroll
    for (int mi = 0; mi < 2; mi++)
#pragma unroll
        for (int ni = 0; ni < 8; ni++)
#pragma unroll
            for (int r = 0; r < 4; r++) acc[mi][ni][r] = 0.f;

    const int lr0 = tid >> 2, lc4 = (tid & 3) * 4;

    auto loadTile = [&](int t, int st) {
        const float* Ap; const float* Bp; int Kc, k0;
        if (t < nt1) { Ap = A;  Bp = B;  Kc = C; k0 = t << 4; }
        else         { Ap = A2; Bp = B2; Kc = H; k0 = (t - nt1) << 4; }
#pragma unroll
        for (int it = 0; it < 2; it++) {
            int rr = lr0 + it * 64;
            int gr = row0 + rr;
            uint32_t dst = (uint32_t)__cvta_generic_to_shared(&Asb[st * 2560 + rr * 20 + lc4]);
            cpa16(dst, Ap + (size_t)gr * Kc + k0 + lc4, gr < NN ? 16 : 0);
        }
#pragma unroll
        for (int it = 0; it < 2; it++) {
            int rr = lr0 + it * 64;                       // tile col 0..127
            int brow = ((rr >> 5) << 8) + c0 + (rr & 31); // gate*256 + c0 + j'
            uint32_t dst = (uint32_t)__cvta_generic_to_shared(&Bsb[st * 2560 + rr * 20 + lc4]);
            cpa16(dst, Bp + (size_t)brow * Kc + k0 + lc4, 16);
        }
    };

    loadTile(0, 0);
    cpa_commit();

    for (int t = 0; t < nt; t++) {
        if (t + 1 < nt) loadTile(t + 1, (t + 1) & 1);
        cpa_commit();
        cpa_wait1();
        __syncthreads();

        const int st = t & 1;
#pragma unroll
        for (int kk = 0; kk < 16; kk += 8) {
            uint32_t a[2][4], b[8][2];
#pragma unroll
            for (int mi = 0; mi < 2; mi++) {
                int mr = wm * 32 + mi * 16;
                a[mi][0] = tfw(Asb[st * 2560 + (mr + gid)     * 20 + kk + tig]);
                a[mi][1] = tfw(Asb[st * 2560 + (mr + gid + 8) * 20 + kk + tig]);
                a[mi][2] = tfw(Asb[st * 2560 + (mr + gid)     * 20 + kk + tig + 4]);
                a[mi][3] = tfw(Asb[st * 2560 + (mr + gid + 8) * 20 + kk + tig + 4]);
            }
#pragma unroll
            for (int ni = 0; ni < 8; ni++) {
                int nr = wn * 64 + ni * 8;
                b[ni][0] = tfw(Bsb[st * 2560 + (nr + gid) * 20 + kk + tig]);
                b[ni][1] = tfw(Bsb[st * 2560 + (nr + gid) * 20 + kk + tig + 4]);
            }
#pragma unroll
            for (int mi = 0; mi < 2; mi++)
#pragma unroll
                for (int ni = 0; ni < 8; ni++)
                    mma8(acc[mi][ni], a[mi], b[ni]);
        }
        __syncthreads();
    }

    // ---- fused epilogue: two 64-row passes through smem ----
    const float* bi = bih + (size_t)dir * H4;
    const float* bh = bhh + (size_t)dir * H4;
    float* lc  = d_lc[dir];
    float* lhw = d_lh[1 - pb][dir];
    const int t_idx = dir ? (4 - s) : s;
    float* aout = (dir ? d_ab : d_af) + t_idx * NN;

#pragma unroll
    for (int p = 0; p < 2; p++) {
        __syncthreads();
        if ((wm >> 1) == p) {
#pragma unroll
            for (int mi = 0; mi < 2; mi++)
#pragma unroll
                for (int half = 0; half < 2; half++) {
                    int rloc = (wm & 1) * 32 + mi * 16 + gid + half * 8;
#pragma unroll
                    for (int ni = 0; ni < 8; ni++) {
                        int col = wn * 64 + ni * 8 + tig * 2;
                        gbuf[rloc * 133 + col]     = acc[mi][ni][half * 2 + 0];
                        gbuf[rloc * 133 + col + 1] = acc[mi][ni][half * 2 + 1];
                    }
                }
        }
        __syncthreads();

        int rr = tid >> 2;                 // 0..63
        int n  = row0 + p * 64 + rr;
        bool valid = n < NN;
        float part = 0.f;
        if (valid) {
            int jb = (tid & 3) * 8;
#pragma unroll
            for (int q = 0; q < 8; q++) {
                int jl = jb + q;           // 0..31
                int j  = c0 + jl;          // 0..255
                float gi = gbuf[rr * 133 +  0 + jl] + bi[0 * H + j] + bh[0 * H + j];
                float gf = gbuf[rr * 133 + 32 + jl] + bi[1 * H + j] + bh[1 * H + j];
                float gg = gbuf[rr * 133 + 64 + jl] + bi[2 * H + j] + bh[2 * H + j];
                float go = gbuf[rr * 133 + 96 + jl] + bi[3 * H + j] + bh[3 * H + j];
                size_t ix = (size_t)n * H + j;
                float cprev = (K2 > 0) ? lc[ix] : 0.f;
                float cc = sigf(gf) * cprev + sigf(gi) * tanhf(gg);
                lc[ix] = cc;
                float hh = sigf(go) * tanhf(cc);
                lhw[ix] = hh;
                part = fmaf(hh, attw[dir * H + j], part);
            }
        }
        part += __shfl_down_sync(0xffffffffu, part, 2);
        part += __shfl_down_sync(0xffffffffu, part, 1);
        if (valid && (tid & 3) == 0) atomicAdd(&aout[n], part);
    }
}

// ---------------- small kernels ----------------
__global__ void k_zero(float* p, int n) {
    int i = blockIdx.x * blockDim.x + threadIdx.x;
    if (i < n) p[i] = 0.f;
}
__global__ void k_zeroi(int* p, int n) {
    int i = blockIdx.x * blockDim.x + threadIdx.x;
    if (i < n) p[i] = 0;
}

__global__ void k_degi(const int* __restrict__ dst) {
    int e = blockIdx.x * blockDim.x + threadIdx.x;
    if (e < NE) atomicAdd(&d_indeg[dst[e]], 1);
}

__global__ void k_scan() {  // 1 block, 1024 threads: exclusive scan of indeg
    const int T = 1024;
    __shared__ int buf[T];
    __shared__ int carry_s;
    int t = threadIdx.x;
    if (t == 0) carry_s = 0;
    __syncthreads();
    for (int base = 0; base < NN; base += T) {
        int v = (base + t < NN) ? d_indeg[base + t] : 0;
        buf[t] = v;
        __syncthreads();
        for (int off = 1; off < T; off <<= 1) {
            int add = (t >= off) ? buf[t - off] : 0;
            __syncthreads();
            buf[t] += add;
            __syncthreads();
        }
        int carry = carry_s;
        __syncthreads();
        if (base + t < NN) {
            d_rowptr[base + t] = carry + buf[t] - v;
            d_curp[base + t]   = carry + buf[t] - v;
        }
        if (t == T - 1) carry_s = carry + buf[t];
        __syncthreads();
    }
    if (t == 0) d_rowptr[NN] = carry_s;
}

__global__ void k_place(const int* __restrict__ src, const int* __restrict__ dst) {
    int e = blockIdx.x * blockDim.x + threadIdx.x;
    if (e >= NE) return;
    int slot = atomicAdd(&d_curp[dst[e]], 1);
    d_eid[slot]  = e;
    d_esrc[slot] = src[e];
}

__global__ void k_ew(const float* __restrict__ ea,
                     const float* __restrict__ mu,
                     const float* __restrict__ sg) {
    int e = blockIdx.x * blockDim.x + threadIdx.x;
    if (e >= NE) return;
    float a0 = ea[e * 2 + 0], a1 = ea[e * 2 + 1];
#pragma unroll
    for (int k = 0; k < KG; k++) {
        float dx = a0 - mu[k * 2 + 0];
        float dy = a1 - mu[k * 2 + 1];
        float s0 = sg[k * 2 + 0], s1 = sg[k * 2 + 1];
        float w = expf(-0.5f * (dx * dx / (1e-15f + s0 * s0) +
                                dy * dy / (1e-15f + s1 * s1)));
        d_ew[(size_t)e * KG + k] = w;
    }
}

// CSR aggregation: one warp per node, registers accumulate; fuses +hr+bias -> h
__global__ void k_aggr(const float* __restrict__ bias) {
    int n = (blockIdx.x * blockDim.x + threadIdx.x) >> 5;
    int l = threadIdx.x & 31;
    if (n >= NN) return;
    int beg = d_rowptr[n], end = d_rowptr[n + 1];
    float a0 = 0.f, a1 = 0.f, a2 = 0.f, a3 = 0.f;
    for (int p = beg; p < end; p++) {
        int e = d_eid[p], s = d_esrc[p];
        float wv = (l < KG) ? d_ew[(size_t)e * KG + l] : 0.f;
        const float* xr = &d_xg[(size_t)s * (KG * C)];
#pragma unroll
        for (int k = 0; k < KG; k++) {
            float wk = __shfl_sync(0xffffffffu, wv, k);
            a0 = fmaf(wk, xr[k * C + l +  0], a0);
            a1 = fmaf(wk, xr[k * C + l + 32], a1);
            a2 = fmaf(wk, xr[k * C + l + 64], a2);
            a3 = fmaf(wk, xr[k * C + l + 96], a3);
        }
    }
    float dg = fmaxf((float)(end - beg), 1.f);
    size_t o = (size_t)n * C;
    d_h[o + l +  0] = a0 / dg + d_hr[o + l +  0] + bias[l +  0];
    d_h[o + l + 32] = a1 / dg + d_hr[o + l + 32] + bias[l + 32];
    d_h[o + l + 64] = a2 / dg + d_hr[o + l + 64] + bias[l + 64];
    d_h[o + l + 96] = a3 / dg + d_hr[o + l + 96] + bias[l + 96];
}

__global__ void k_bnred() {  // <<<128,128>>>
    int c = threadIdx.x;
    float s = 0.f, q = 0.f;
    for (int r = blockIdx.x; r < NN; r += gridDim.x) {
        float v = d_h[(size_t)r * C + c];
        s += v; q += v * v;
    }
    atomicAdd(&d_bns[c], s);
    atomicAdd(&d_bnq[c], q);
}

__global__ void k_bnapp(const float* __restrict__ gamma,
                        const float* __restrict__ beta,
                        float* __restrict__ out_hl, int relu) {
    int i = blockIdx.x * blockDim.x + threadIdx.x;
    if (i >= NN * C) return;
    int c = i % C;
    float mean = d_bns[c] / (float)NN;
    float var  = d_bnq[c] / (float)NN - mean * mean;
    float v = (d_h[i] - mean) * rsqrtf(var + 1e-5f) * gamma[c] + beta[c];
    if (relu) v = fmaxf(v, 0.f);
    d_h[i] = v;
    out_hl[i] = v;
}

// softmax over 5 layer-scores per node + weighted sum of h_list
__global__ void k_nrep(const float* __restrict__ x) {
    int n = blockIdx.x;
    int c = threadIdx.x;
    __shared__ float p[5];
    if (c == 0) {
        float a[5], m = -1e30f;
#pragma unroll
        for (int t = 0; t < 5; t++) {
            a[t] = d_af[t * NN + n] + d_ab[t * NN + n];
            m = fmaxf(m, a[t]);
        }
        float s = 0.f;
#pragma unroll
        for (int t = 0; t < 5; t++) { a[t] = expf(a[t] - m); s += a[t]; }
#pragma unroll
        for (int t = 0; t < 5; t++) p[t] = a[t] / s;
    }
    __syncthreads();
    float r = p[0] * x[(size_t)n * C + c];
#pragma unroll
    for (int t = 1; t < 5; t++) r = fmaf(p[t], d_hl[t - 1][(size_t)n * C + c], r);
    d_nrep[(size_t)n * C + c] = r;
}

__global__ void k_cnt(const int* __restrict__ batch) {
    int n = blockIdx.x * blockDim.x + threadIdx.x;
    if (n < NN) atomicAdd(&d_cnt[batch[n]], 1.f);
}

__global__ void k_pool(const int* __restrict__ batch) {
    int i = blockIdx.x * blockDim.x + threadIdx.x;
    if (i >= NN * C) return;
    int n = i / C, c = i % C;
    atomicAdd(&d_hg[(size_t)batch[n] * C + c], d_nrep[i]);
}

__global__ void k_pdiv() {
    int i = blockIdx.x * blockDim.x + threadIdx.x;
    if (i >= NB * C) return;
    d_hg[i] /= fmaxf(d_cnt[i / C], 1.f);
}

__global__ void k_ln(const float* __restrict__ g, const float* __restrict__ b,
                     float* __restrict__ out) {  // <<<NB, NOUT>>>
    int row = blockIdx.x, t = threadIdx.x;
    __shared__ float sm[NOUT];
    float v = d_z2[(size_t)row * NOUT + t];
    sm[t] = v;
    __syncthreads();
    for (int o = NOUT / 2; o > 0; o >>= 1) {
        if (t < o) sm[t] += sm[t + o];
        __syncthreads();
    }
    float mean = sm[0] / (float)NOUT;
    __syncthreads();
    float dv = v - mean;
    sm[t] = dv * dv;
    __syncthreads();
    for (int o = NOUT / 2; o > 0; o >>= 1) {
        if (t < o) sm[t] += sm[t + o];
        __syncthreads();
    }
    float var = sm[0] / (float)NOUT;
    out[(size_t)row * NOUT + t] = dv * rsqrtf(var + 1e-5f) * g[t] + b[t];
}

// ---------------- host ----------------
static float* symf(const void* s) {
    void* p = nullptr;
    cudaGetSymbolAddress(&p, s);
    return (float*)p;
}
static int* symi(const void* s) {
    void* p = nullptr;
    cudaGetSymbolAddress(&p, s);
    return (int*)p;
}

extern "C" void kernel_launch(void* const* d_in, const int* in_sizes, int n_in,
                              void* d_out, int out_size) {
    const float* x     = (const float*)d_in[0];
    const int*   ei    = (const int*)d_in[1];
    const int*   src   = ei;
    const int*   dst   = ei + NE;
    const float* ea    = (const float*)d_in[2];
    const int*   batch = (const int*)d_in[3];
    const float* g     = (const float*)d_in[4];
    const float* root  = (const float*)d_in[5];
    const float* bias  = (const float*)d_in[6];
    const float* mu    = (const float*)d_in[7];
    const float* sigma = (const float*)d_in[8];
    const float* bng   = (const float*)d_in[9];
    const float* bnb   = (const float*)d_in[10];
    const float* wih   = (const float*)d_in[11];
    const float* whh   = (const float*)d_in[12];
    const float* bih   = (const float*)d_in[13];
    const float* bhh   = (const float*)d_in[14];
    const float* attw  = (const float*)d_in[15];
    const float* p1w   = (const float*)d_in[17];
    const float* p1b   = (const float*)d_in[18];
    const float* p2w   = (const float*)d_in[19];
    const float* p2b   = (const float*)d_in[20];
    const float* lng   = (const float*)d_in[21];
    const float* lnb   = (const float*)d_in[22];
    float* out = (float*)d_out;

    float* h   = symf(d_h);
    float* hl  = symf(d_hl);
    float* xg  = symf(d_xg);
    float* hr  = symf(d_hr);
    float* bns = symf(d_bns);
    float* bnq = symf(d_bnq);
    float* lc  = symf(d_lc);
    float* af  = symf(d_af);
    float* ab  = symf(d_ab);
    float* cnt = symf(d_cnt);
    float* hg  = symf(d_hg);
    float* z1  = symf(d_z1);
    float* z2  = symf(d_z2);
    int* indeg = symi(d_indeg);

    const int TPB = 256;
    const dim3 blk(TPB);
    const int gridNC = (NN * C + TPB - 1) / TPB;
    const int rowsN  = (NN + 127) / 128;

    // -------- CSR build (once per call; graph constant across layers) -----
    k_zeroi<<<(NN + TPB - 1) / TPB, blk>>>(indeg, NN);
    k_degi<<<(NE + TPB - 1) / TPB, blk>>>(dst);
    k_scan<<<1, 1024>>>();
    k_place<<<(NE + TPB - 1) / TPB, blk>>>(src, dst);

    // -------- GMMConv layers --------
    const float* hin = x;
    for (int i = 0; i < LL; i++) {
        GA gxg = {hin, g + (size_t)i * C * KG * C, nullptr, nullptr, xg};
        tgemm<false, false, false, false>
            <<<dim3((KG * C) / 128, rowsN, 1), blk>>>(gxg, gxg, nullptr, NN, KG * C, C, 0);
        k_ew<<<(NE + TPB - 1) / TPB, blk>>>(ea, mu + i * KG * 2, sigma + i * KG * 2);
        GA grt = {hin, root + (size_t)i * C * C, nullptr, nullptr, hr};
        tgemm<false, false, false, false>
            <<<dim3(1, rowsN, 1), blk>>>(grt, grt, nullptr, NN, C, C, 0);
        k_aggr<<<(NN * 32 + TPB - 1) / TPB, blk>>>(bias + i * C);
        k_zero<<<1, C>>>(bns, C);
        k_zero<<<1, C>>>(bnq, C);
        k_bnred<<<128, 128>>>();
        k_bnapp<<<gridNC, blk>>>(bng + i * C, bnb + i * C, hl + (size_t)i * NN * C,
                                 (i < LL - 1) ? 1 : 0);
        hin = h;
    }

    // -------- bidirectional LSTM JumpingKnowledge (fused GEMM+cell) -------
    k_zero<<<(5 * NN + TPB - 1) / TPB, blk>>>(af, 5 * NN);
    k_zero<<<(5 * NN + TPB - 1) / TPB, blk>>>(ab, 5 * NN);
    for (int s = 0; s < 5; s++) {
        int tf = s, tb = 4 - s;
        const float* xf = (tf == 0) ? x : (hl + (size_t)(tf - 1) * NN * C);
        const float* xb = (tb == 0) ? x : (hl + (size_t)(tb - 1) * NN * C);
        tlstm<<<dim3(H / 32, rowsN, 2), blk>>>(xf, xb, wih, whh, bih, bhh, attw,
                                               (s > 0) ? H : 0, s);
    }

    // attention softmax + weighted node representation
    k_nrep<<<NN, C>>>(x);

    // global mean pool
    k_zero<<<(NB + TPB - 1) / TPB, blk>>>(cnt, NB);
    k_zero<<<(NB * C + TPB - 1) / TPB, blk>>>(hg, NB * C);
    k_cnt<<<(NN + TPB - 1) / TPB, blk>>>(batch);
    k_pool<<<gridNC, blk>>>(batch);
    k_pdiv<<<(NB * C + TPB - 1) / TPB, blk>>>();

    // MLP + LayerNorm
    GA gp1 = {hg, p1w, nullptr, nullptr, z1};
    tgemm<false, false, true, true>
        <<<dim3(NHID / 128, NB / 128, 1), blk>>>(gp1, gp1, p1b, NB, NHID, C, 0);
    GA gp2 = {z1, p2w, nullptr, nullptr, z2};
    tgemm<false, false, false, true>
        <<<dim3(NOUT / 128, NB / 128, 1), blk>>>(gp2, gp2, p2b, NB, NOUT, NHID, 0);
    k_ln<<<NB, NOUT>>>(lng, lnb, out);
}

// round 5
// speedup vs baseline: 1.2671x; 1.2671x over previous
#include <cuda_runtime.h>
#include <math.h>
#include <stdint.h>

// ---------------- problem constants ----------------
namespace {
constexpr int NN   = 30000;   // nodes
constexpr int NE   = 480000;  // edges
constexpr int C    = 128;     // channels (= F)
constexpr int KG   = 8;       // gaussians
constexpr int LL   = 4;       // layers
constexpr int H    = 256;     // LSTM hidden
constexpr int H4   = 1024;    // 4*H
constexpr int NHID = 512;
constexpr int NOUT = 256;
constexpr int NB   = 1024;    // graphs
}

// ---------------- scratch (device globals; no allocations allowed) -------
__device__ __align__(256) float d_h[NN * C];
__device__ __align__(256) float d_hl[LL][NN * C];
__device__ __align__(256) float d_S[NN * KG * C];     // per-node weighted sums
__device__ __align__(256) float d_gt[LL][KG * C * C]; // g transposed: [(k,f)][c]
__device__ __align__(256) float d_ew[NE * KG];
__device__ __align__(256) float d_bns[C];
__device__ __align__(256) float d_bnq[C];
__device__ __align__(256) float d_lh[2][2][NN * H];   // [pingpong][dir]
__device__ __align__(256) float d_lc[2][NN * H];      // [dir]
__device__ __align__(256) float d_af[5 * NN];
__device__ __align__(256) float d_ab[5 * NN];
__device__ __align__(256) float d_nrep[NN * C];
__device__ __align__(256) float d_cnt[NB];
__device__ __align__(256) float d_hg[NB * C];
__device__ __align__(256) float d_z1[NB * NHID];
__device__ __align__(256) float d_z2[NB * NOUT];
// CSR scratch
__device__ __align__(256) int d_indeg[NN];
__device__ __align__(256) int d_rowptr[NN + 1];
__device__ __align__(256) int d_curp[NN];
__device__ __align__(256) int d_eid[NE];
__device__ __align__(256) int d_esrc[NE];

// ---------------- TF32 helpers ----------------
__device__ __forceinline__ uint32_t f2tf(float f) {
    uint32_t u;
    asm("cvt.rna.tf32.f32 %0, %1;" : "=r"(u) : "f"(f));
    return u;
}
__device__ __forceinline__ uint32_t tfw(uint32_t rawbits) {
    return f2tf(__uint_as_float(rawbits));
}
__device__ __forceinline__ void mma8(float* c, const uint32_t* a, const uint32_t* b) {
    asm volatile(
        "mma.sync.aligned.m16n8k8.row.col.f32.tf32.tf32.f32 "
        "{%0,%1,%2,%3}, {%4,%5,%6,%7}, {%8,%9}, {%0,%1,%2,%3};"
        : "+f"(c[0]), "+f"(c[1]), "+f"(c[2]), "+f"(c[3])
        : "r"(a[0]), "r"(a[1]), "r"(a[2]), "r"(a[3]), "r"(b[0]), "r"(b[1]));
}
__device__ __forceinline__ void cpa16(uint32_t sdst, const void* gsrc, int srcsz) {
    asm volatile("cp.async.ca.shared.global [%0], [%1], 16, %2;\n"
                 :: "r"(sdst), "l"(gsrc), "r"(srcsz));
}
__device__ __forceinline__ void cpa_commit() { asm volatile("cp.async.commit_group;\n"); }
__device__ __forceinline__ void cpa_wait1()  { asm volatile("cp.async.wait_group 1;\n"); }
__device__ __forceinline__ float sigf(float x) { return 1.f / (1.f + expf(-x)); }

// ---------------- generic TF32 GEMM (cp.async 2-stage, dual-K) ----------
struct GA {
    const float* A;   // [M, Kd]
    const float* B;   // TB: [Nm, Kd]  else [Kd, Nm]
    const float* A2;  // [M, Kd2]
    const float* B2;  // TB: [Nm, Kd2] else [Kd2, Nm]
    float* Cm;        // [M, Nm]
};

template <bool TB, bool ACC, bool RELU_, bool BIAS_>
__global__ __launch_bounds__(256) void tgemm(
    GA g0, GA g1, const float* __restrict__ bias, int M, int Nm, int Kd, int Kd2)
{
    __shared__ uint32_t As[2][128 * 20];
    __shared__ uint32_t Bs[2][2560];

    const GA ga = blockIdx.z ? g1 : g0;
    const float* __restrict__ A  = ga.A;
    const float* __restrict__ B  = ga.B;
    const float* __restrict__ A2 = ga.A2;
    const float* __restrict__ B2 = ga.B2;
    float* __restrict__ Cm = ga.Cm;

    const int tid  = threadIdx.x;
    const int lane = tid & 31;
    const int wid  = tid >> 5;
    const int wm   = wid & 3;
    const int wn   = wid >> 2;
    const int gid  = lane >> 2;
    const int tig  = lane & 3;
    const int row0 = blockIdx.y * 128, col0 = blockIdx.x * 128;

    const int nt1 = Kd >> 4;
    const int nt  = nt1 + (Kd2 >> 4);

    float acc[2][8][4];
#pragma unroll
    for (int mi = 0; mi < 2; mi++)
#pragma unroll
        for (int ni = 0; ni < 8; ni++)
#pragma unroll
            for (int r = 0; r < 4; r++) acc[mi][ni][r] = 0.f;

    const int lr0 = tid >> 2, lc4 = (tid & 3) * 4;

    auto loadTile = [&](int t, int st) {
        const float* Ap; const float* Bp; int Kc, k0;
        if (t < nt1) { Ap = A;  Bp = B;  Kc = Kd;  k0 = t << 4; }
        else         { Ap = A2; Bp = B2; Kc = Kd2; k0 = (t - nt1) << 4; }
#pragma unroll
        for (int it = 0; it < 2; it++) {
            int rr = lr0 + it * 64;
            int gr = row0 + rr;
            uint32_t dst = (uint32_t)__cvta_generic_to_shared(&As[st][rr * 20 + lc4]);
            cpa16(dst, Ap + (size_t)gr * Kc + k0 + lc4, gr < M ? 16 : 0);
        }
        if (TB) {
#pragma unroll
            for (int it = 0; it < 2; it++) {
                int rr = lr0 + it * 64;
                uint32_t dst = (uint32_t)__cvta_generic_to_shared(&Bs[st][rr * 20 + lc4]);
                cpa16(dst, Bp + (size_t)(col0 + rr) * Kc + k0 + lc4, 16);
            }
        } else {
#pragma unroll
            for (int it = 0; it < 2; it++) {
                int idx = tid + it * 256;
                int kk = idx >> 5, n4 = (idx & 31) * 4;
                uint32_t dst = (uint32_t)__cvta_generic_to_shared(&Bs[st][kk * 136 + n4]);
                cpa16(dst, Bp + (size_t)(k0 + kk) * Nm + col0 + n4, 16);
            }
        }
    };

    loadTile(0, 0);
    cpa_commit();

    for (int t = 0; t < nt; t++) {
        if (t + 1 < nt) loadTile(t + 1, (t + 1) & 1);
        cpa_commit();
        cpa_wait1();
        __syncthreads();

        const int st = t & 1;
#pragma unroll
        for (int kk = 0; kk < 16; kk += 8) {
            uint32_t a[2][4], b[8][2];
#pragma unroll
            for (int mi = 0; mi < 2; mi++) {
                int mr = wm * 32 + mi * 16;
                a[mi][0] = tfw(As[st][(mr + gid)     * 20 + kk + tig]);
                a[mi][1] = tfw(As[st][(mr + gid + 8) * 20 + kk + tig]);
                a[mi][2] = tfw(As[st][(mr + gid)     * 20 + kk + tig + 4]);
                a[mi][3] = tfw(As[st][(mr + gid + 8) * 20 + kk + tig + 4]);
            }
#pragma unroll
            for (int ni = 0; ni < 8; ni++) {
                int nr = wn * 64 + ni * 8;
                if (TB) {
                    b[ni][0] = tfw(Bs[st][(nr + gid) * 20 + kk + tig]);
                    b[ni][1] = tfw(Bs[st][(nr + gid) * 20 + kk + tig + 4]);
                } else {
                    b[ni][0] = tfw(Bs[st][(kk + tig)     * 136 + nr + gid]);
                    b[ni][1] = tfw(Bs[st][(kk + tig + 4) * 136 + nr + gid]);
                }
            }
#pragma unroll
            for (int mi = 0; mi < 2; mi++)
#pragma unroll
                for (int ni = 0; ni < 8; ni++)
                    mma8(acc[mi][ni], a[mi], b[ni]);
        }
        __syncthreads();
    }

#pragma unroll
    for (int mi = 0; mi < 2; mi++) {
#pragma unroll
        for (int half = 0; half < 2; half++) {
            int r = row0 + wm * 32 + mi * 16 + gid + half * 8;
            if (r >= M) continue;
#pragma unroll
            for (int ni = 0; ni < 8; ni++) {
                int cI = col0 + wn * 64 + ni * 8 + tig * 2;
                float v0 = acc[mi][ni][half * 2 + 0];
                float v1 = acc[mi][ni][half * 2 + 1];
                float* cp = Cm + (size_t)r * Nm + cI;
                if (ACC)   { v0 += cp[0]; v1 += cp[1]; }
                if (BIAS_) { v0 += bias[cI]; v1 += bias[cI + 1]; }
                if (RELU_) { v0 = fmaxf(v0, 0.f); v1 = fmaxf(v1, 0.f); }
                cp[0] = v0; cp[1] = v1;
            }
        }
    }
}

// ---------------- fused LSTM step: GEMM + cell + attention dot ----------
__global__ __launch_bounds__(256) void tlstm(
    const float* __restrict__ xf, const float* __restrict__ xb,
    const float* __restrict__ wih, const float* __restrict__ whh,
    const float* __restrict__ bih, const float* __restrict__ bhh,
    const float* __restrict__ attw, int K2, int s)
{
    __shared__ __align__(16) uint32_t sraw[10240];
    uint32_t* Asb = sraw;
    uint32_t* Bsb = sraw + 5120;
    float* gbuf = (float*)sraw;      // epilogue reuse: [64][133]

    const int dir  = blockIdx.z;
    const int c0   = blockIdx.x * 32;
    const int row0 = blockIdx.y * 128;
    const int pb   = s & 1;

    const float* A  = dir ? xb : xf;
    const float* B  = wih + (size_t)dir * H4 * C;
    const float* A2 = d_lh[pb][dir];
    const float* B2 = whh + (size_t)dir * H4 * H;

    const int tid  = threadIdx.x;
    const int lane = tid & 31;
    const int wid  = tid >> 5;
    const int wm   = wid & 3;
    const int wn   = wid >> 2;
    const int gid  = lane >> 2;
    const int tig  = lane & 3;

    const int nt1 = C >> 4;
    const int nt  = nt1 + (K2 >> 4);

    float acc[2][8][4];
#pragma unroll
    for (int mi = 0; mi < 2; mi++)
#pragma unroll
        for (int ni = 0; ni < 8; ni++)
#pragma unroll
            for (int r = 0; r < 4; r++) acc[mi][ni][r] = 0.f;

    const int lr0 = tid >> 2, lc4 = (tid & 3) * 4;

    auto loadTile = [&](int t, int st) {
        const float* Ap; const float* Bp; int Kc, k0;
        if (t < nt1) { Ap = A;  Bp = B;  Kc = C; k0 = t << 4; }
        else         { Ap = A2; Bp = B2; Kc = H; k0 = (t - nt1) << 4; }
#pragma unroll
        for (int it = 0; it < 2; it++) {
            int rr = lr0 + it * 64;
            int gr = row0 + rr;
            uint32_t dst = (uint32_t)__cvta_generic_to_shared(&Asb[st * 2560 + rr * 20 + lc4]);
            cpa16(dst, Ap + (size_t)gr * Kc + k0 + lc4, gr < NN ? 16 : 0);
        }
#pragma unroll
        for (int it = 0; it < 2; it++) {
            int rr = lr0 + it * 64;
            int brow = ((rr >> 5) << 8) + c0 + (rr & 31);
            uint32_t dst = (uint32_t)__cvta_generic_to_shared(&Bsb[st * 2560 + rr * 20 + lc4]);
            cpa16(dst, Bp + (size_t)brow * Kc + k0 + lc4, 16);
        }
    };

    loadTile(0, 0);
    cpa_commit();

    for (int t = 0; t < nt; t++) {
        if (t + 1 < nt) loadTile(t + 1, (t + 1) & 1);
        cpa_commit();
        cpa_wait1();
        __syncthreads();

        const int st = t & 1;
#pragma unroll
        for (int kk = 0; kk < 16; kk += 8) {
            uint32_t a[2][4], b[8][2];
#pragma unroll
            for (int mi = 0; mi < 2; mi++) {
                int mr = wm * 32 + mi * 16;
                a[mi][0] = tfw(Asb[st * 2560 + (mr + gid)     * 20 + kk + tig]);
                a[mi][1] = tfw(Asb[st * 2560 + (mr + gid + 8) * 20 + kk + tig]);
                a[mi][2] = tfw(Asb[st * 2560 + (mr + gid)     * 20 + kk + tig + 4]);
                a[mi][3] = tfw(Asb[st * 2560 + (mr + gid + 8) * 20 + kk + tig + 4]);
            }
#pragma unroll
            for (int ni = 0; ni < 8; ni++) {
                int nr = wn * 64 + ni * 8;
                b[ni][0] = tfw(Bsb[st * 2560 + (nr + gid) * 20 + kk + tig]);
                b[ni][1] = tfw(Bsb[st * 2560 + (nr + gid) * 20 + kk + tig + 4]);
            }
#pragma unroll
            for (int mi = 0; mi < 2; mi++)
#pragma unroll
                for (int ni = 0; ni < 8; ni++)
                    mma8(acc[mi][ni], a[mi], b[ni]);
        }
        __syncthreads();
    }

    const float* bi = bih + (size_t)dir * H4;
    const float* bh = bhh + (size_t)dir * H4;
    float* lc  = d_lc[dir];
    float* lhw = d_lh[1 - pb][dir];
    const int t_idx = dir ? (4 - s) : s;
    float* aout = (dir ? d_ab : d_af) + t_idx * NN;

#pragma unroll
    for (int p = 0; p < 2; p++) {
        __syncthreads();
        if ((wm >> 1) == p) {
#pragma unroll
            for (int mi = 0; mi < 2; mi++)
#pragma unroll
                for (int half = 0; half < 2; half++) {
                    int rloc = (wm & 1) * 32 + mi * 16 + gid + half * 8;
#pragma unroll
                    for (int ni = 0; ni < 8; ni++) {
                        int col = wn * 64 + ni * 8 + tig * 2;
                        gbuf[rloc * 133 + col]     = acc[mi][ni][half * 2 + 0];
                        gbuf[rloc * 133 + col + 1] = acc[mi][ni][half * 2 + 1];
                    }
                }
        }
        __syncthreads();

        int rr = tid >> 2;
        int n  = row0 + p * 64 + rr;
        bool valid = n < NN;
        float part = 0.f;
        if (valid) {
            int jb = (tid & 3) * 8;
#pragma unroll
            for (int q = 0; q < 8; q++) {
                int jl = jb + q;
                int j  = c0 + jl;
                float gi = gbuf[rr * 133 +  0 + jl] + bi[0 * H + j] + bh[0 * H + j];
                float gf = gbuf[rr * 133 + 32 + jl] + bi[1 * H + j] + bh[1 * H + j];
                float gg = gbuf[rr * 133 + 64 + jl] + bi[2 * H + j] + bh[2 * H + j];
                float go = gbuf[rr * 133 + 96 + jl] + bi[3 * H + j] + bh[3 * H + j];
                size_t ix = (size_t)n * H + j;
                float cprev = (K2 > 0) ? lc[ix] : 0.f;
                float cc = sigf(gf) * cprev + sigf(gi) * tanhf(gg);
                lc[ix] = cc;
                float hh = sigf(go) * tanhf(cc);
                lhw[ix] = hh;
                part = fmaf(hh, attw[dir * H + j], part);
            }
        }
        part += __shfl_down_sync(0xffffffffu, part, 2);
        part += __shfl_down_sync(0xffffffffu, part, 1);
        if (valid && (tid & 3) == 0) atomicAdd(&aout[n], part);
    }
}

// ---------------- small kernels ----------------
__global__ void k_zero(float* p, int n) {
    int i = blockIdx.x * blockDim.x + threadIdx.x;
    if (i < n) p[i] = 0.f;
}
__global__ void k_zeroi(int* p, int n) {
    int i = blockIdx.x * blockDim.x + threadIdx.x;
    if (i < n) p[i] = 0;
}

__global__ void k_degi(const int* __restrict__ dst) {
    int e = blockIdx.x * blockDim.x + threadIdx.x;
    if (e < NE) atomicAdd(&d_indeg[dst[e]], 1);
}

__global__ void k_scan() {  // 1 block, 1024 threads
    const int T = 1024;
    __shared__ int buf[T];
    __shared__ int carry_s;
    int t = threadIdx.x;
    if (t == 0) carry_s = 0;
    __syncthreads();
    for (int base = 0; base < NN; base += T) {
        int v = (base + t < NN) ? d_indeg[base + t] : 0;
        buf[t] = v;
        __syncthreads();
        for (int off = 1; off < T; off <<= 1) {
            int add = (t >= off) ? buf[t - off] : 0;
            __syncthreads();
            buf[t] += add;
            __syncthreads();
        }
        int carry = carry_s;
        __syncthreads();
        if (base + t < NN) {
            d_rowptr[base + t] = carry + buf[t] - v;
            d_curp[base + t]   = carry + buf[t] - v;
        }
        if (t == T - 1) carry_s = carry + buf[t];
        __syncthreads();
    }
    if (t == 0) d_rowptr[NN] = carry_s;
}

__global__ void k_place(const int* __restrict__ src, const int* __restrict__ dst) {
    int e = blockIdx.x * blockDim.x + threadIdx.x;
    if (e >= NE) return;
    int slot = atomicAdd(&d_curp[dst[e]], 1);
    d_eid[slot]  = e;
    d_esrc[slot] = src[e];
}

// g: [L][F=128][K*C=1024] -> gT: [L][(k*128+f)][c]
__global__ void k_gt(const float* __restrict__ g) {
    int i = blockIdx.x * blockDim.x + threadIdx.x;
    if (i >= LL * C * KG * C) return;
    int l  = i / (C * KG * C);
    int r  = (i / (KG * C)) % C;       // f
    int kc = i % (KG * C);
    int k = kc / C, c = kc % C;
    d_gt[l][(k * C + r) * C + c] = g[i];
}

__global__ void k_ew(const float* __restrict__ ea,
                     const float* __restrict__ mu,
                     const float* __restrict__ sg) {
    int e = blockIdx.x * blockDim.x + threadIdx.x;
    if (e >= NE) return;
    float a0 = ea[e * 2 + 0], a1 = ea[e * 2 + 1];
#pragma unroll
    for (int k = 0; k < KG; k++) {
        float dx = a0 - mu[k * 2 + 0];
        float dy = a1 - mu[k * 2 + 1];
        float s0 = sg[k * 2 + 0], s1 = sg[k * 2 + 1];
        float w = expf(-0.5f * (dx * dx / (1e-15f + s0 * s0) +
                                dy * dy / (1e-15f + s1 * s1)));
        d_ew[(size_t)e * KG + k] = w;
    }
}

// S accumulation: warp per node. S[n,k,f] = (sum_{e in(n)} w[e,k]*hin[src,f])/deg
// gathers only 512B/edge from hin (L2-resident) instead of 4KB/edge from xg.
__global__ void k_sacc(const float* __restrict__ hin) {
    int n = (blockIdx.x * blockDim.x + threadIdx.x) >> 5;
    int l = threadIdx.x & 31;
    if (n >= NN) return;
    int beg = d_rowptr[n], end = d_rowptr[n + 1];
    float acc[KG][4];
#pragma unroll
    for (int k = 0; k < KG; k++)
#pragma unroll
        for (int q = 0; q < 4; q++) acc[k][q] = 0.f;

    for (int p = beg; p < end; p++) {
        int e = d_eid[p], s = d_esrc[p];
        float wv = (l < KG) ? d_ew[(size_t)e * KG + l] : 0.f;
        const float* hrp = hin + (size_t)s * C;
        float hv0 = hrp[l], hv1 = hrp[l + 32], hv2 = hrp[l + 64], hv3 = hrp[l + 96];
#pragma unroll
        for (int k = 0; k < KG; k++) {
            float wk = __shfl_sync(0xffffffffu, wv, k);
            acc[k][0] = fmaf(wk, hv0, acc[k][0]);
            acc[k][1] = fmaf(wk, hv1, acc[k][1]);
            acc[k][2] = fmaf(wk, hv2, acc[k][2]);
            acc[k][3] = fmaf(wk, hv3, acc[k][3]);
        }
    }
    float inv = 1.f / fmaxf((float)(end - beg), 1.f);
    float* Sp = &d_S[(size_t)n * (KG * C)];
#pragma unroll
    for (int k = 0; k < KG; k++) {
        Sp[k * C + l +  0] = acc[k][0] * inv;
        Sp[k * C + l + 32] = acc[k][1] * inv;
        Sp[k * C + l + 64] = acc[k][2] * inv;
        Sp[k * C + l + 96] = acc[k][3] * inv;
    }
}

__global__ void k_bnred() {  // <<<128,128>>>
    int c = threadIdx.x;
    float s = 0.f, q = 0.f;
    for (int r = blockIdx.x; r < NN; r += gridDim.x) {
        float v = d_h[(size_t)r * C + c];
        s += v; q += v * v;
    }
    atomicAdd(&d_bns[c], s);
    atomicAdd(&d_bnq[c], q);
}

__global__ void k_bnapp(const float* __restrict__ gamma,
                        const float* __restrict__ beta,
                        float* __restrict__ out_hl, int relu) {
    int i = blockIdx.x * blockDim.x + threadIdx.x;
    if (i >= NN * C) return;
    int c = i % C;
    float mean = d_bns[c] / (float)NN;
    float var  = d_bnq[c] / (float)NN - mean * mean;
    float v = (d_h[i] - mean) * rsqrtf(var + 1e-5f) * gamma[c] + beta[c];
    if (relu) v = fmaxf(v, 0.f);
    d_h[i] = v;
    out_hl[i] = v;
}

// softmax over 5 layer-scores per node + weighted sum of h_list
__global__ void k_nrep(const float* __restrict__ x) {
    int n = blockIdx.x;
    int c = threadIdx.x;
    __shared__ float p[5];
    if (c == 0) {
        float a[5], m = -1e30f;
#pragma unroll
        for (int t = 0; t < 5; t++) {
            a[t] = d_af[t * NN + n] + d_ab[t * NN + n];
            m = fmaxf(m, a[t]);
        }
        float s = 0.f;
#pragma unroll
        for (int t = 0; t < 5; t++) { a[t] = expf(a[t] - m); s += a[t]; }
#pragma unroll
        for (int t = 0; t < 5; t++) p[t] = a[t] / s;
    }
    __syncthreads();
    float r = p[0] * x[(size_t)n * C + c];
#pragma unroll
    for (int t = 1; t < 5; t++) r = fmaf(p[t], d_hl[t - 1][(size_t)n * C + c], r);
    d_nrep[(size_t)n * C + c] = r;
}

__global__ void k_cnt(const int* __restrict__ batch) {
    int n = blockIdx.x * blockDim.x + threadIdx.x;
    if (n < NN) atomicAdd(&d_cnt[batch[n]], 1.f);
}

__global__ void k_pool(const int* __restrict__ batch) {
    int i = blockIdx.x * blockDim.x + threadIdx.x;
    if (i >= NN * C) return;
    int n = i / C, c = i % C;
    atomicAdd(&d_hg[(size_t)batch[n] * C + c], d_nrep[i]);
}

__global__ void k_pdiv() {
    int i = blockIdx.x * blockDim.x + threadIdx.x;
    if (i >= NB * C) return;
    d_hg[i] /= fmaxf(d_cnt[i / C], 1.f);
}

__global__ void k_ln(const float* __restrict__ g, const float* __restrict__ b,
                     float* __restrict__ out) {  // <<<NB, NOUT>>>
    int row = blockIdx.x, t = threadIdx.x;
    __shared__ float sm[NOUT];
    float v = d_z2[(size_t)row * NOUT + t];
    sm[t] = v;
    __syncthreads();
    for (int o = NOUT / 2; o > 0; o >>= 1) {
        if (t < o) sm[t] += sm[t + o];
        __syncthreads();
    }
    float mean = sm[0] / (float)NOUT;
    __syncthreads();
    float dv = v - mean;
    sm[t] = dv * dv;
    __syncthreads();
    for (int o = NOUT / 2; o > 0; o >>= 1) {
        if (t < o) sm[t] += sm[t + o];
        __syncthreads();
    }
    float var = sm[0] / (float)NOUT;
    out[(size_t)row * NOUT + t] = dv * rsqrtf(var + 1e-5f) * g[t] + b[t];
}

// ---------------- host ----------------
static float* symf(const void* s) {
    void* p = nullptr;
    cudaGetSymbolAddress(&p, s);
    return (float*)p;
}
static int* symi(const void* s) {
    void* p = nullptr;
    cudaGetSymbolAddress(&p, s);
    return (int*)p;
}

extern "C" void kernel_launch(void* const* d_in, const int* in_sizes, int n_in,
                              void* d_out, int out_size) {
    const float* x     = (const float*)d_in[0];
    const int*   ei    = (const int*)d_in[1];
    const int*   src   = ei;
    const int*   dst   = ei + NE;
    const float* ea    = (const float*)d_in[2];
    const int*   batch = (const int*)d_in[3];
    const float* g     = (const float*)d_in[4];
    const float* root  = (const float*)d_in[5];
    const float* bias  = (const float*)d_in[6];
    const float* mu    = (const float*)d_in[7];
    const float* sigma = (const float*)d_in[8];
    const float* bng   = (const float*)d_in[9];
    const float* bnb   = (const float*)d_in[10];
    const float* wih   = (const float*)d_in[11];
    const float* whh   = (const float*)d_in[12];
    const float* bih   = (const float*)d_in[13];
    const float* bhh   = (const float*)d_in[14];
    const float* attw  = (const float*)d_in[15];
    const float* p1w   = (const float*)d_in[17];
    const float* p1b   = (const float*)d_in[18];
    const float* p2w   = (const float*)d_in[19];
    const float* p2b   = (const float*)d_in[20];
    const float* lng   = (const float*)d_in[21];
    const float* lnb   = (const float*)d_in[22];
    float* out = (float*)d_out;

    float* h   = symf(d_h);
    float* hl  = symf(d_hl);
    float* S   = symf(d_S);
    float* gt  = symf(d_gt);
    float* bns = symf(d_bns);
    float* bnq = symf(d_bnq);
    float* af  = symf(d_af);
    float* ab  = symf(d_ab);
    float* cnt = symf(d_cnt);
    float* hg  = symf(d_hg);
    float* z1  = symf(d_z1);
    float* z2  = symf(d_z2);
    int* indeg = symi(d_indeg);

    const int TPB = 256;
    const dim3 blk(TPB);
    const int gridNC = (NN * C + TPB - 1) / TPB;
    const int rowsN  = (NN + 127) / 128;

    // -------- CSR build + g transpose (graph/weights constant across layers)
    k_zeroi<<<(NN + TPB - 1) / TPB, blk>>>(indeg, NN);
    k_degi<<<(NE + TPB - 1) / TPB, blk>>>(dst);
    k_scan<<<1, 1024>>>();
    k_place<<<(NE + TPB - 1) / TPB, blk>>>(src, dst);
    k_gt<<<(LL * C * KG * C + TPB - 1) / TPB, blk>>>(g);

    // -------- GMMConv layers --------
    const float* hin = x;
    for (int i = 0; i < LL; i++) {
        k_ew<<<(NE + TPB - 1) / TPB, blk>>>(ea, mu + i * KG * 2, sigma + i * KG * 2);
        k_sacc<<<(NN * 32 + TPB - 1) / TPB, blk>>>(hin);
        // h = S @ gT[i]  +  hin @ root[i]  + bias[i]   (dual-K, in-place safe)
        GA gl = {S, gt + (size_t)i * KG * C * C, hin, root + (size_t)i * C * C, h};
        tgemm<false, false, false, true>
            <<<dim3(1, rowsN, 1), blk>>>(gl, gl, bias + i * C, NN, C, KG * C, C);
        k_zero<<<1, C>>>(bns, C);
        k_zero<<<1, C>>>(bnq, C);
        k_bnred<<<128, 128>>>();
        k_bnapp<<<gridNC, blk>>>(bng + i * C, bnb + i * C, hl + (size_t)i * NN * C,
                                 (i < LL - 1) ? 1 : 0);
        hin = h;
    }

    // -------- bidirectional LSTM JumpingKnowledge (fused GEMM+cell) -------
    k_zero<<<(5 * NN + TPB - 1) / TPB, blk>>>(af, 5 * NN);
    k_zero<<<(5 * NN + TPB - 1) / TPB, blk>>>(ab, 5 * NN);
    for (int s = 0; s < 5; s++) {
        int tf = s, tb = 4 - s;
        const float* xf = (tf == 0) ? x : (hl + (size_t)(tf - 1) * NN * C);
        const float* xb = (tb == 0) ? x : (hl + (size_t)(tb - 1) * NN * C);
        tlstm<<<dim3(H / 32, rowsN, 2), blk>>>(xf, xb, wih, whh, bih, bhh, attw,
                                               (s > 0) ? H : 0, s);
    }

    // attention softmax + weighted node representation
    k_nrep<<<NN, C>>>(x);

    // global mean pool
    k_zero<<<(NB + TPB - 1) / TPB, blk>>>(cnt, NB);
    k_zero<<<(NB * C + TPB - 1) / TPB, blk>>>(hg, NB * C);
    k_cnt<<<(NN + TPB - 1) / TPB, blk>>>(batch);
    k_pool<<<gridNC, blk>>>(batch);
    k_pdiv<<<(NB * C + TPB - 1) / TPB, blk>>>();

    // MLP + LayerNorm
    GA gp1 = {hg, p1w, nullptr, nullptr, z1};
    tgemm<false, false, true, true>
        <<<dim3(NHID / 128, NB / 128, 1), blk>>>(gp1, gp1, p1b, NB, NHID, C, 0);
    GA gp2 = {z1, p2w, nullptr, nullptr, z2};
    tgemm<false, false, false, true>
        <<<dim3(NOUT / 128, NB / 128, 1), blk>>>(gp2, gp2, p2b, NB, NOUT, NHID, 0);
    k_ln<<<NB, NOUT>>>(lng, lnb, out);
}

// round 6
// speedup vs baseline: 1.2681x; 1.0008x over previous
#include <cuda_runtime.h>
#include <math.h>
#include <stdint.h>

// ---------------- problem constants ----------------
namespace {
constexpr int NN   = 30000;   // nodes
constexpr int NE   = 480000;  // edges
constexpr int C    = 128;     // channels (= F)
constexpr int KG   = 8;       // gaussians
constexpr int LL   = 4;       // layers
constexpr int H    = 256;     // LSTM hidden
constexpr int H4   = 1024;    // 4*H
constexpr int NHID = 512;
constexpr int NOUT = 256;
constexpr int NB   = 1024;    // graphs
}

// ---------------- scratch (device globals; no allocations allowed) -------
__device__ __align__(256) float d_h[NN * C];
__device__ __align__(256) float d_hl[LL][NN * C];
__device__ __align__(256) float d_hlt[5][NN * C];     // tf32-valued x,h1..h4
__device__ __align__(256) float d_S[NN * KG * C];
__device__ __align__(256) float d_gt[LL][KG * C * C];
__device__ __align__(256) float d_ew[NE * KG];
__device__ __align__(256) float d_bns[C];
__device__ __align__(256) float d_bnq[C];
__device__ __align__(256) float d_lh[2][2][NN * H];   // tf32-valued, [pp][dir]
__device__ __align__(256) float d_lc[2][NN * H];
__device__ __align__(256) float d_af[5 * NN];
__device__ __align__(256) float d_ab[5 * NN];
__device__ __align__(256) float d_nrep[NN * C];
__device__ __align__(256) float d_cnt[NB];
__device__ __align__(256) float d_hg[NB * C];
__device__ __align__(256) float d_z1[NB * NHID];
__device__ __align__(256) float d_z2[NB * NOUT];
// tf32-valued LSTM weights + fused biases
__device__ __align__(256) float d_wiht[2 * H4 * C];
__device__ __align__(256) float d_whht[2 * H4 * H];
__device__ __align__(256) float d_bsum[2 * H4];
// CSR scratch
__device__ __align__(256) int d_indeg[NN];
__device__ __align__(256) int d_rowptr[NN + 1];
__device__ __align__(256) int d_curp[NN];
__device__ __align__(256) int d_eid[NE];
__device__ __align__(256) int d_esrc[NE];

// ---------------- TF32 helpers ----------------
__device__ __forceinline__ uint32_t f2tf(float f) {
    uint32_t u;
    asm("cvt.rna.tf32.f32 %0, %1;" : "=r"(u) : "f"(f));
    return u;
}
__device__ __forceinline__ uint32_t tfw(uint32_t rawbits) {
    return f2tf(__uint_as_float(rawbits));
}
__device__ __forceinline__ void mma8(float* c, const uint32_t* a, const uint32_t* b) {
    asm volatile(
        "mma.sync.aligned.m16n8k8.row.col.f32.tf32.tf32.f32 "
        "{%0,%1,%2,%3}, {%4,%5,%6,%7}, {%8,%9}, {%0,%1,%2,%3};"
        : "+f"(c[0]), "+f"(c[1]), "+f"(c[2]), "+f"(c[3])
        : "r"(a[0]), "r"(a[1]), "r"(a[2]), "r"(a[3]), "r"(b[0]), "r"(b[1]));
}
__device__ __forceinline__ void cpa16(uint32_t sdst, const void* gsrc, int srcsz) {
    asm volatile("cp.async.ca.shared.global [%0], [%1], 16, %2;\n"
                 :: "r"(sdst), "l"(gsrc), "r"(srcsz));
}
__device__ __forceinline__ void cpa_commit() { asm volatile("cp.async.commit_group;\n"); }
__device__ __forceinline__ void cpa_wait1()  { asm volatile("cp.async.wait_group 1;\n"); }
__device__ __forceinline__ float sigf(float x) { return 1.f / (1.f + expf(-x)); }

// ---------------- generic TF32 GEMM (cp.async 2-stage, dual-K) ----------
struct GA {
    const float* A;
    const float* B;
    const float* A2;
    const float* B2;
    float* Cm;
};

template <bool TB, bool ACC, bool RELU_, bool BIAS_>
__global__ __launch_bounds__(256) void tgemm(
    GA g0, GA g1, const float* __restrict__ bias, int M, int Nm, int Kd, int Kd2)
{
    __shared__ uint32_t As[2][128 * 20];
    __shared__ uint32_t Bs[2][2560];

    const GA ga = blockIdx.z ? g1 : g0;
    const float* __restrict__ A  = ga.A;
    const float* __restrict__ B  = ga.B;
    const float* __restrict__ A2 = ga.A2;
    const float* __restrict__ B2 = ga.B2;
    float* __restrict__ Cm = ga.Cm;

    const int tid  = threadIdx.x;
    const int lane = tid & 31;
    const int wid  = tid >> 5;
    const int wm   = wid & 3;
    const int wn   = wid >> 2;
    const int gid  = lane >> 2;
    const int tig  = lane & 3;
    const int row0 = blockIdx.y * 128, col0 = blockIdx.x * 128;

    const int nt1 = Kd >> 4;
    const int nt  = nt1 + (Kd2 >> 4);

    float acc[2][8][4];
#pragma unroll
    for (int mi = 0; mi < 2; mi++)
#pragma unroll
        for (int ni = 0; ni < 8; ni++)
#pragma unroll
            for (int r = 0; r < 4; r++) acc[mi][ni][r] = 0.f;

    const int lr0 = tid >> 2, lc4 = (tid & 3) * 4;

    auto loadTile = [&](int t, int st) {
        const float* Ap; const float* Bp; int Kc, k0;
        if (t < nt1) { Ap = A;  Bp = B;  Kc = Kd;  k0 = t << 4; }
        else         { Ap = A2; Bp = B2; Kc = Kd2; k0 = (t - nt1) << 4; }
#pragma unroll
        for (int it = 0; it < 2; it++) {
            int rr = lr0 + it * 64;
            int gr = row0 + rr;
            uint32_t dst = (uint32_t)__cvta_generic_to_shared(&As[st][rr * 20 + lc4]);
            cpa16(dst, Ap + (size_t)gr * Kc + k0 + lc4, gr < M ? 16 : 0);
        }
        if (TB) {
#pragma unroll
            for (int it = 0; it < 2; it++) {
                int rr = lr0 + it * 64;
                uint32_t dst = (uint32_t)__cvta_generic_to_shared(&Bs[st][rr * 20 + lc4]);
                cpa16(dst, Bp + (size_t)(col0 + rr) * Kc + k0 + lc4, 16);
            }
        } else {
#pragma unroll
            for (int it = 0; it < 2; it++) {
                int idx = tid + it * 256;
                int kk = idx >> 5, n4 = (idx & 31) * 4;
                uint32_t dst = (uint32_t)__cvta_generic_to_shared(&Bs[st][kk * 136 + n4]);
                cpa16(dst, Bp + (size_t)(k0 + kk) * Nm + col0 + n4, 16);
            }
        }
    };

    loadTile(0, 0);
    cpa_commit();

    for (int t = 0; t < nt; t++) {
        if (t + 1 < nt) loadTile(t + 1, (t + 1) & 1);
        cpa_commit();
        cpa_wait1();
        __syncthreads();

        const int st = t & 1;
#pragma unroll
        for (int kk = 0; kk < 16; kk += 8) {
            uint32_t a[2][4], b[8][2];
#pragma unroll
            for (int mi = 0; mi < 2; mi++) {
                int mr = wm * 32 + mi * 16;
                a[mi][0] = tfw(As[st][(mr + gid)     * 20 + kk + tig]);
                a[mi][1] = tfw(As[st][(mr + gid + 8) * 20 + kk + tig]);
                a[mi][2] = tfw(As[st][(mr + gid)     * 20 + kk + tig + 4]);
                a[mi][3] = tfw(As[st][(mr + gid + 8) * 20 + kk + tig + 4]);
            }
#pragma unroll
            for (int ni = 0; ni < 8; ni++) {
                int nr = wn * 64 + ni * 8;
                if (TB) {
                    b[ni][0] = tfw(Bs[st][(nr + gid) * 20 + kk + tig]);
                    b[ni][1] = tfw(Bs[st][(nr + gid) * 20 + kk + tig + 4]);
                } else {
                    b[ni][0] = tfw(Bs[st][(kk + tig)     * 136 + nr + gid]);
                    b[ni][1] = tfw(Bs[st][(kk + tig + 4) * 136 + nr + gid]);
                }
            }
#pragma unroll
            for (int mi = 0; mi < 2; mi++)
#pragma unroll
                for (int ni = 0; ni < 8; ni++)
                    mma8(acc[mi][ni], a[mi], b[ni]);
        }
        __syncthreads();
    }

#pragma unroll
    for (int mi = 0; mi < 2; mi++) {
#pragma unroll
        for (int half = 0; half < 2; half++) {
            int r = row0 + wm * 32 + mi * 16 + gid + half * 8;
            if (r >= M) continue;
#pragma unroll
            for (int ni = 0; ni < 8; ni++) {
                int cI = col0 + wn * 64 + ni * 8 + tig * 2;
                float v0 = acc[mi][ni][half * 2 + 0];
                float v1 = acc[mi][ni][half * 2 + 1];
                float* cp = Cm + (size_t)r * Nm + cI;
                if (ACC)   { v0 += cp[0]; v1 += cp[1]; }
                if (BIAS_) { v0 += bias[cI]; v1 += bias[cI + 1]; }
                if (RELU_) { v0 = fmaxf(v0, 0.f); v1 = fmaxf(v1, 0.f); }
                cp[0] = v0; cp[1] = v1;
            }
        }
    }
}

// ---------------- fused LSTM step: GEMM + cell + attention dot ----------
// All GEMM inputs are pre-converted tf32-valued floats -> no cvt in hot loop.
__global__ __launch_bounds__(256) void tlstm(
    const float* __restrict__ xf, const float* __restrict__ xb,
    const float* __restrict__ attw, int K2, int s)
{
    __shared__ __align__(16) uint32_t sraw[10240];
    uint32_t* Asb = sraw;
    uint32_t* Bsb = sraw + 5120;
    float* gbuf = (float*)sraw;      // epilogue reuse: [64][133]

    const int dir  = blockIdx.z;
    const int c0   = blockIdx.x * 32;
    const int row0 = blockIdx.y * 128;
    const int pb   = s & 1;

    const float* A  = dir ? xb : xf;
    const float* B  = d_wiht + (size_t)dir * H4 * C;
    const float* A2 = d_lh[pb][dir];
    const float* B2 = d_whht + (size_t)dir * H4 * H;

    const int tid  = threadIdx.x;
    const int lane = tid & 31;
    const int wid  = tid >> 5;
    const int wm   = wid & 3;
    const int wn   = wid >> 2;
    const int gid  = lane >> 2;
    const int tig  = lane & 3;

    const int nt1 = C >> 4;
    const int nt  = nt1 + (K2 >> 4);

    float acc[2][8][4];
#pragma unroll
    for (int mi = 0; mi < 2; mi++)
#pragma unroll
        for (int ni = 0; ni < 8; ni++)
#pragma unroll
            for (int r = 0; r < 4; r++) acc[mi][ni][r] = 0.f;

    const int lr0 = tid >> 2, lc4 = (tid & 3) * 4;

    auto loadTile = [&](int t, int st) {
        const float* Ap; const float* Bp; int Kc, k0;
        if (t < nt1) { Ap = A;  Bp = B;  Kc = C; k0 = t << 4; }
        else         { Ap = A2; Bp = B2; Kc = H; k0 = (t - nt1) << 4; }
#pragma unroll
        for (int it = 0; it < 2; it++) {
            int rr = lr0 + it * 64;
            int gr = row0 + rr;
            uint32_t dst = (uint32_t)__cvta_generic_to_shared(&Asb[st * 2560 + rr * 20 + lc4]);
            cpa16(dst, Ap + (size_t)gr * Kc + k0 + lc4, gr < NN ? 16 : 0);
        }
#pragma unroll
        for (int it = 0; it < 2; it++) {
            int rr = lr0 + it * 64;
            int brow = ((rr >> 5) << 8) + c0 + (rr & 31);
            uint32_t dst = (uint32_t)__cvta_generic_to_shared(&Bsb[st * 2560 + rr * 20 + lc4]);
            cpa16(dst, Bp + (size_t)brow * Kc + k0 + lc4, 16);
        }
    };

    loadTile(0, 0);
    cpa_commit();

    for (int t = 0; t < nt; t++) {
        if (t + 1 < nt) loadTile(t + 1, (t + 1) & 1);
        cpa_commit();
        cpa_wait1();
        __syncthreads();

        const int st = t & 1;
#pragma unroll
        for (int kk = 0; kk < 16; kk += 8) {
            uint32_t a[2][4], b[8][2];
#pragma unroll
            for (int mi = 0; mi < 2; mi++) {
                int mr = wm * 32 + mi * 16;
                a[mi][0] = Asb[st * 2560 + (mr + gid)     * 20 + kk + tig];
                a[mi][1] = Asb[st * 2560 + (mr + gid + 8) * 20 + kk + tig];
                a[mi][2] = Asb[st * 2560 + (mr + gid)     * 20 + kk + tig + 4];
                a[mi][3] = Asb[st * 2560 + (mr + gid + 8) * 20 + kk + tig + 4];
            }
#pragma unroll
            for (int ni = 0; ni < 8; ni++) {
                int nr = wn * 64 + ni * 8;
                b[ni][0] = Bsb[st * 2560 + (nr + gid) * 20 + kk + tig];
                b[ni][1] = Bsb[st * 2560 + (nr + gid) * 20 + kk + tig + 4];
            }
#pragma unroll
            for (int mi = 0; mi < 2; mi++)
#pragma unroll
                for (int ni = 0; ni < 8; ni++)
                    mma8(acc[mi][ni], a[mi], b[ni]);
        }
        __syncthreads();
    }

    const float* bs = d_bsum + (size_t)dir * H4;
    float* lc  = d_lc[dir];
    float* lhw = d_lh[1 - pb][dir];
    const int t_idx = dir ? (4 - s) : s;
    float* aout = (dir ? d_ab : d_af) + t_idx * NN;

#pragma unroll
    for (int p = 0; p < 2; p++) {
        __syncthreads();
        if ((wm >> 1) == p) {
#pragma unroll
            for (int mi = 0; mi < 2; mi++)
#pragma unroll
                for (int half = 0; half < 2; half++) {
                    int rloc = (wm & 1) * 32 + mi * 16 + gid + half * 8;
#pragma unroll
                    for (int ni = 0; ni < 8; ni++) {
                        int col = wn * 64 + ni * 8 + tig * 2;
                        gbuf[rloc * 133 + col]     = acc[mi][ni][half * 2 + 0];
                        gbuf[rloc * 133 + col + 1] = acc[mi][ni][half * 2 + 1];
                    }
                }
        }
        __syncthreads();

        int rr = tid >> 2;
        int n  = row0 + p * 64 + rr;
        bool valid = n < NN;
        float part = 0.f;
        if (valid) {
            int jb = (tid & 3) * 8;
#pragma unroll
            for (int q = 0; q < 8; q++) {
                int jl = jb + q;
                int j  = c0 + jl;
                float gi = gbuf[rr * 133 +  0 + jl] + bs[0 * H + j];
                float gf = gbuf[rr * 133 + 32 + jl] + bs[1 * H + j];
                float gg = gbuf[rr * 133 + 64 + jl] + bs[2 * H + j];
                float go = gbuf[rr * 133 + 96 + jl] + bs[3 * H + j];
                size_t ix = (size_t)n * H + j;
                float cprev = (K2 > 0) ? lc[ix] : 0.f;
                float cc = sigf(gf) * cprev + sigf(gi) * tanhf(gg);
                lc[ix] = cc;
                float hh = sigf(go) * tanhf(cc);
                lhw[ix] = __uint_as_float(f2tf(hh));   // store tf32-valued
                part = fmaf(hh, attw[dir * H + j], part);
            }
        }
        part += __shfl_down_sync(0xffffffffu, part, 2);
        part += __shfl_down_sync(0xffffffffu, part, 1);
        if (valid && (tid & 3) == 0) atomicAdd(&aout[n], part);
    }
}

// ---------------- small kernels ----------------
__global__ void k_zero(float* p, int n) {
    int i = blockIdx.x * blockDim.x + threadIdx.x;
    if (i < n) p[i] = 0.f;
}
__global__ void k_zeroi(int* p, int n) {
    int i = blockIdx.x * blockDim.x + threadIdx.x;
    if (i < n) p[i] = 0;
}

__global__ void k_degi(const int* __restrict__ dst) {
    int e = blockIdx.x * blockDim.x + threadIdx.x;
    if (e < NE) atomicAdd(&d_indeg[dst[e]], 1);
}

__global__ void k_scan() {
    const int T = 1024;
    __shared__ int buf[T];
    __shared__ int carry_s;
    int t = threadIdx.x;
    if (t == 0) carry_s = 0;
    __syncthreads();
    for (int base = 0; base < NN; base += T) {
        int v = (base + t < NN) ? d_indeg[base + t] : 0;
        buf[t] = v;
        __syncthreads();
        for (int off = 1; off < T; off <<= 1) {
            int add = (t >= off) ? buf[t - off] : 0;
            __syncthreads();
            buf[t] += add;
            __syncthreads();
        }
        int carry = carry_s;
        __syncthreads();
        if (base + t < NN) {
            d_rowptr[base + t] = carry + buf[t] - v;
            d_curp[base + t]   = carry + buf[t] - v;
        }
        if (t == T - 1) carry_s = carry + buf[t];
        __syncthreads();
    }
    if (t == 0) d_rowptr[NN] = carry_s;
}

__global__ void k_place(const int* __restrict__ src, const int* __restrict__ dst) {
    int e = blockIdx.x * blockDim.x + threadIdx.x;
    if (e >= NE) return;
    int slot = atomicAdd(&d_curp[dst[e]], 1);
    d_eid[slot]  = e;
    d_esrc[slot] = src[e];
}

__global__ void k_gt(const float* __restrict__ g) {
    int i = blockIdx.x * blockDim.x + threadIdx.x;
    if (i >= LL * C * KG * C) return;
    int l  = i / (C * KG * C);
    int r  = (i / (KG * C)) % C;
    int kc = i % (KG * C);
    int k = kc / C, c = kc % C;
    d_gt[l][(k * C + r) * C + c] = g[i];
}

// pre-convert LSTM weights to tf32-valued floats; fuse biases; cvt x
__global__ void k_cvtw(const float* __restrict__ wih, const float* __restrict__ whh,
                       const float* __restrict__ bih, const float* __restrict__ bhh,
                       const float* __restrict__ x) {
    int i = blockIdx.x * blockDim.x + threadIdx.x;
    if (i < 2 * H4 * C) d_wiht[i] = __uint_as_float(f2tf(wih[i]));
    if (i < 2 * H4 * H) d_whht[i] = __uint_as_float(f2tf(whh[i]));
    if (i < 2 * H4)     d_bsum[i] = bih[i] + bhh[i];
    if (i < NN * C)     d_hlt[0][i] = __uint_as_float(f2tf(x[i]));
}

__global__ void k_ew(const float* __restrict__ ea,
                     const float* __restrict__ mu,
                     const float* __restrict__ sg) {
    int e = blockIdx.x * blockDim.x + threadIdx.x;
    if (e >= NE) return;
    float a0 = ea[e * 2 + 0], a1 = ea[e * 2 + 1];
#pragma unroll
    for (int k = 0; k < KG; k++) {
        float dx = a0 - mu[k * 2 + 0];
        float dy = a1 - mu[k * 2 + 1];
        float s0 = sg[k * 2 + 0], s1 = sg[k * 2 + 1];
        float w = expf(-0.5f * (dx * dx / (1e-15f + s0 * s0) +
                                dy * dy / (1e-15f + s1 * s1)));
        d_ew[(size_t)e * KG + k] = w;
    }
}

__global__ void k_sacc(const float* __restrict__ hin) {
    int n = (blockIdx.x * blockDim.x + threadIdx.x) >> 5;
    int l = threadIdx.x & 31;
    if (n >= NN) return;
    int beg = d_rowptr[n], end = d_rowptr[n + 1];
    float acc[KG][4];
#pragma unroll
    for (int k = 0; k < KG; k++)
#pragma unroll
        for (int q = 0; q < 4; q++) acc[k][q] = 0.f;

    for (int p = beg; p < end; p++) {
        int e = d_eid[p], s = d_esrc[p];
        float wv = (l < KG) ? d_ew[(size_t)e * KG + l] : 0.f;
        const float* hrp = hin + (size_t)s * C;
        float hv0 = hrp[l], hv1 = hrp[l + 32], hv2 = hrp[l + 64], hv3 = hrp[l + 96];
#pragma unroll
        for (int k = 0; k < KG; k++) {
            float wk = __shfl_sync(0xffffffffu, wv, k);
            acc[k][0] = fmaf(wk, hv0, acc[k][0]);
            acc[k][1] = fmaf(wk, hv1, acc[k][1]);
            acc[k][2] = fmaf(wk, hv2, acc[k][2]);
            acc[k][3] = fmaf(wk, hv3, acc[k][3]);
        }
    }
    float inv = 1.f / fmaxf((float)(end - beg), 1.f);
    float* Sp = &d_S[(size_t)n * (KG * C)];
#pragma unroll
    for (int k = 0; k < KG; k++) {
        Sp[k * C + l +  0] = acc[k][0] * inv;
        Sp[k * C + l + 32] = acc[k][1] * inv;
        Sp[k * C + l + 64] = acc[k][2] * inv;
        Sp[k * C + l + 96] = acc[k][3] * inv;
    }
}

__global__ void k_bnred() {  // <<<128,128>>>
    int c = threadIdx.x;
    float s = 0.f, q = 0.f;
    for (int r = blockIdx.x; r < NN; r += gridDim.x) {
        float v = d_h[(size_t)r * C + c];
        s += v; q += v * v;
    }
    atomicAdd(&d_bns[c], s);
    atomicAdd(&d_bnq[c], q);
}

__global__ void k_bnapp(const float* __restrict__ gamma,
                        const float* __restrict__ beta,
                        float* __restrict__ out_hl,
                        float* __restrict__ out_hlt, int relu) {
    int i = blockIdx.x * blockDim.x + threadIdx.x;
    if (i >= NN * C) return;
    int c = i % C;
    float mean = d_bns[c] / (float)NN;
    float var  = d_bnq[c] / (float)NN - mean * mean;
    float v = (d_h[i] - mean) * rsqrtf(var + 1e-5f) * gamma[c] + beta[c];
    if (relu) v = fmaxf(v, 0.f);
    d_h[i] = v;
    out_hl[i]  = v;
    out_hlt[i] = __uint_as_float(f2tf(v));
}

__global__ void k_nrep(const float* __restrict__ x) {
    int n = blockIdx.x;
    int c = threadIdx.x;
    __shared__ float p[5];
    if (c == 0) {
        float a[5], m = -1e30f;
#pragma unroll
        for (int t = 0; t < 5; t++) {
            a[t] = d_af[t * NN + n] + d_ab[t * NN + n];
            m = fmaxf(m, a[t]);
        }
        float s = 0.f;
#pragma unroll
        for (int t = 0; t < 5; t++) { a[t] = expf(a[t] - m); s += a[t]; }
#pragma unroll
        for (int t = 0; t < 5; t++) p[t] = a[t] / s;
    }
    __syncthreads();
    float r = p[0] * x[(size_t)n * C + c];
#pragma unroll
    for (int t = 1; t < 5; t++) r = fmaf(p[t], d_hl[t - 1][(size_t)n * C + c], r);
    d_nrep[(size_t)n * C + c] = r;
}

__global__ void k_cnt(const int* __restrict__ batch) {
    int n = blockIdx.x * blockDim.x + threadIdx.x;
    if (n < NN) atomicAdd(&d_cnt[batch[n]], 1.f);
}

__global__ void k_pool(const int* __restrict__ batch) {
    int i = blockIdx.x * blockDim.x + threadIdx.x;
    if (i >= NN * C) return;
    int n = i / C, c = i % C;
    atomicAdd(&d_hg[(size_t)batch[n] * C + c], d_nrep[i]);
}

__global__ void k_pdiv() {
    int i = blockIdx.x * blockDim.x + threadIdx.x;
    if (i >= NB * C) return;
    d_hg[i] /= fmaxf(d_cnt[i / C], 1.f);
}

__global__ void k_ln(const float* __restrict__ g, const float* __restrict__ b,
                     float* __restrict__ out) {
    int row = blockIdx.x, t = threadIdx.x;
    __shared__ float sm[NOUT];
    float v = d_z2[(size_t)row * NOUT + t];
    sm[t] = v;
    __syncthreads();
    for (int o = NOUT / 2; o > 0; o >>= 1) {
        if (t < o) sm[t] += sm[t + o];
        __syncthreads();
    }
    float mean = sm[0] / (float)NOUT;
    __syncthreads();
    float dv = v - mean;
    sm[t] = dv * dv;
    __syncthreads();
    for (int o = NOUT / 2; o > 0; o >>= 1) {
        if (t < o) sm[t] += sm[t + o];
        __syncthreads();
    }
    float var = sm[0] / (float)NOUT;
    out[(size_t)row * NOUT + t] = dv * rsqrtf(var + 1e-5f) * g[t] + b[t];
}

// ---------------- host ----------------
static float* symf(const void* s) {
    void* p = nullptr;
    cudaGetSymbolAddress(&p, s);
    return (float*)p;
}
static int* symi(const void* s) {
    void* p = nullptr;
    cudaGetSymbolAddress(&p, s);
    return (int*)p;
}

extern "C" void kernel_launch(void* const* d_in, const int* in_sizes, int n_in,
                              void* d_out, int out_size) {
    const float* x     = (const float*)d_in[0];
    const int*   ei    = (const int*)d_in[1];
    const int*   src   = ei;
    const int*   dst   = ei + NE;
    const float* ea    = (const float*)d_in[2];
    const int*   batch = (const int*)d_in[3];
    const float* g     = (const float*)d_in[4];
    const float* root  = (const float*)d_in[5];
    const float* bias  = (const float*)d_in[6];
    const float* mu    = (const float*)d_in[7];
    const float* sigma = (const float*)d_in[8];
    const float* bng   = (const float*)d_in[9];
    const float* bnb   = (const float*)d_in[10];
    const float* wih   = (const float*)d_in[11];
    const float* whh   = (const float*)d_in[12];
    const float* bih   = (const float*)d_in[13];
    const float* bhh   = (const float*)d_in[14];
    const float* attw  = (const float*)d_in[15];
    const float* p1w   = (const float*)d_in[17];
    const float* p1b   = (const float*)d_in[18];
    const float* p2w   = (const float*)d_in[19];
    const float* p2b   = (const float*)d_in[20];
    const float* lng   = (const float*)d_in[21];
    const float* lnb   = (const float*)d_in[22];
    float* out = (float*)d_out;

    float* h   = symf(d_h);
    float* hl  = symf(d_hl);
    float* hlt = symf(d_hlt);
    float* S   = symf(d_S);
    float* gt  = symf(d_gt);
    float* bns = symf(d_bns);
    float* bnq = symf(d_bnq);
    float* af  = symf(d_af);
    float* ab  = symf(d_ab);
    float* cnt = symf(d_cnt);
    float* hg  = symf(d_hg);
    float* z1  = symf(d_z1);
    float* z2  = symf(d_z2);
    int* indeg = symi(d_indeg);

    const int TPB = 256;
    const dim3 blk(TPB);
    const int gridNC = (NN * C + TPB - 1) / TPB;
    const int rowsN  = (NN + 127) / 128;

    // -------- CSR build + weight prep --------
    k_zeroi<<<(NN + TPB - 1) / TPB, blk>>>(indeg, NN);
    k_degi<<<(NE + TPB - 1) / TPB, blk>>>(dst);
    k_scan<<<1, 1024>>>();
    k_place<<<(NE + TPB - 1) / TPB, blk>>>(src, dst);
    k_gt<<<(LL * C * KG * C + TPB - 1) / TPB, blk>>>(g);
    {
        int mx = NN * C;                       // 3.84M threads covers all arrays
        k_cvtw<<<(mx + TPB - 1) / TPB, blk>>>(wih, whh, bih, bhh, x);
    }

    // -------- GMMConv layers --------
    const float* hin = x;
    for (int i = 0; i < LL; i++) {
        k_ew<<<(NE + TPB - 1) / TPB, blk>>>(ea, mu + i * KG * 2, sigma + i * KG * 2);
        k_sacc<<<(NN * 32 + TPB - 1) / TPB, blk>>>(hin);
        GA gl = {S, gt + (size_t)i * KG * C * C, hin, root + (size_t)i * C * C, h};
        tgemm<false, false, false, true>
            <<<dim3(1, rowsN, 1), blk>>>(gl, gl, bias + i * C, NN, C, KG * C, C);
        k_zero<<<1, C>>>(bns, C);
        k_zero<<<1, C>>>(bnq, C);
        k_bnred<<<128, 128>>>();
        k_bnapp<<<gridNC, blk>>>(bng + i * C, bnb + i * C,
                                 hl + (size_t)i * NN * C,
                                 hlt + (size_t)(i + 1) * NN * C,
                                 (i < LL - 1) ? 1 : 0);
        hin = h;
    }

    // -------- bidirectional LSTM JumpingKnowledge (fused GEMM+cell) -------
    k_zero<<<(5 * NN + TPB - 1) / TPB, blk>>>(af, 5 * NN);
    k_zero<<<(5 * NN + TPB - 1) / TPB, blk>>>(ab, 5 * NN);
    for (int s = 0; s < 5; s++) {
        int tf = s, tb = 4 - s;
        const float* xf = hlt + (size_t)tf * NN * C;
        const float* xb = hlt + (size_t)tb * NN * C;
        tlstm<<<dim3(H / 32, rowsN, 2), blk>>>(xf, xb, attw, (s > 0) ? H : 0, s);
    }

    // attention softmax + weighted node representation
    k_nrep<<<NN, C>>>(x);

    // global mean pool
    k_zero<<<(NB + TPB - 1) / TPB, blk>>>(cnt, NB);
    k_zero<<<(NB * C + TPB - 1) / TPB, blk>>>(hg, NB * C);
    k_cnt<<<(NN + TPB - 1) / TPB, blk>>>(batch);
    k_pool<<<gridNC, blk>>>(batch);
    k_pdiv<<<(NB * C + TPB - 1) / TPB, blk>>>();

    // MLP + LayerNorm
    GA gp1 = {hg, p1w, nullptr, nullptr, z1};
    tgemm<false, false, true, true>
        <<<dim3(NHID / 128, NB / 128, 1), blk>>>(gp1, gp1, p1b, NB, NHID, C, 0);
    GA gp2 = {z1, p2w, nullptr, nullptr, z2};
    tgemm<false, false, false, true>
        <<<dim3(NOUT / 128, NB / 128, 1), blk>>>(gp2, gp2, p2b, NB, NOUT, NHID, 0);
    k_ln<<<NB, NOUT>>>(lng, lnb, out);
}